// round 9
// baseline (speedup 1.0000x reference)
#include <cuda_runtime.h>
#include <cuda_fp16.h>
#include <cstdint>

#define SIGINV 50.0f     // 1 / (2 * 0.1^2)
#define EPSs   1e-8f

// Separable RBF tables (fp32), fp16 features in NATURAL layout [b][n][e]
__device__ float  g_ex[4][64][4096];
__device__ float  g_ey[4][64][4096];
__device__ __half g_fth[4][4096][256];

// ---------------- helpers ----------------
__device__ __forceinline__ uint32_t smem_u32(const void* p) {
    uint32_t a;
    asm("{ .reg .u64 t; cvta.to.shared.u64 t, %1; cvt.u32.u64 %0, t; }"
        : "=r"(a) : "l"(p));
    return a;
}
__device__ __forceinline__ uint32_t f16x2(float hi, float lo) {
    uint32_t r;
    asm("cvt.rn.f16x2.f32 %0, %1, %2;" : "=r"(r) : "f"(hi), "f"(lo));
    return r;
}

// ---------------- pre-kernels ----------------
__global__ void __launch_bounds__(256) table_kernel(const float* __restrict__ pos) {
    int b = blockIdx.x >> 6, gi = blockIdx.x & 63;
    float gc = (float)gi * (1.0f / 63.0f);
    int t = threadIdx.x;
    const float2* p2 = (const float2*)pos + (size_t)b * 4096;
#pragma unroll
    for (int j = 0; j < 16; j++) {
        int n = t + j * 256;
        float2 p = p2[n];
        float dx = gc - p.x, dy = gc - p.y;
        g_ex[b][gi][n] = __expf(-SIGINV * dx * dx);
        g_ey[b][gi][n] = __expf(-SIGINV * dy * dy);
    }
}

// streaming fp32 -> fp16 convert, natural layout (no transpose needed)
__global__ void __launch_bounds__(256) convert_kernel(const float* __restrict__ feat) {
    size_t i = ((size_t)blockIdx.x * 256 + threadIdx.x) * 8;
    float4 f0 = *(const float4*)(feat + i);
    float4 f1 = *(const float4*)(feat + i + 4);
    uint32_t h0 = f16x2(f0.y, f0.x), h1 = f16x2(f0.w, f0.z);
    uint32_t h2 = f16x2(f1.y, f1.x), h3 = f16x2(f1.w, f1.z);
    *(uint4*)(&g_fth[0][0][0] + i) = make_uint4(h0, h1, h2, h3);
}

// ---------------- main mma.sync fp16 kernel ----------------
// 256 blocks: blk = b*64 + mt*2 + et. Block tile: 128p x 128e.
// K chunks of 64 (4x m16n8k16 k-steps). 8 warps, warp tile 32p x 64e.
// A (W tile): [128p][64k] fp16, pitch 144 B. B (F tile): [64k][128e], pitch 272 B.
// Frags via ldmatrix (A: .x4, B: .x4.trans) — conflict-free by pitch rotation.
#define APITCH 144
#define BPITCH 272
#define BOFFR  (128 * APITCH)            // 18432
#define STAGE  (BOFFR + 64 * BPITCH)     // 35840
#define SMEMT  (2 * STAGE)               // 71680

__global__ void __launch_bounds__(256, 2) mma_kernel(float* __restrict__ out) {
    extern __shared__ char smem[];
    uint32_t sb = smem_u32(smem);
    const int t = threadIdx.x, w = t >> 5, l = t & 31;
    const int blk = blockIdx.x, b = blk >> 6, mt = (blk >> 1) & 31, et = blk & 1;

    // --- staging maps ---
    const int sr = t >> 1, h = t & 1;          // W: 2 threads/row, 32 k each
    const float* exrow = &g_ex[b][mt * 2 + (sr >> 6)][0];
    const float* eyrow = &g_ey[b][sr & 63][0];
    const uint32_t wsAddr = sb + sr * APITCH + h * 64;
    const __half* ftp = &g_fth[b][t >> 2][et * 128 + (t & 3) * 32];  // F: 4 thr/row
    const uint32_t fsAddr = sb + BOFFR + (t >> 2) * BPITCH + (t & 3) * 64;

    // --- mma fragment maps: wm 0..3 (32p), wn 0..1 (64e) ---
    const int wm = w & 3, wn = w >> 2, g = l >> 2, tig = l & 3;
    const uint32_t aLane = (uint32_t)((wm * 32 + (l & 15)) * APITCH + ((l >> 4) * 8) * 2);
    const uint32_t bLane = (uint32_t)((l & 15) * BPITCH + (wn * 64 + (l >> 4) * 8) * 2);

    float acc[2][8][4];
#pragma unroll
    for (int i = 0; i < 2; i++)
#pragma unroll
        for (int j = 0; j < 8; j++)
#pragma unroll
            for (int q = 0; q < 4; q++) acc[i][j][q] = 0.0f;
    float psum = 0.0f;

#define STAGE_CHUNK(c, s)                                                     \
    do {                                                                      \
        const uint32_t so = (s) * STAGE;                                      \
        const int nc = (c) * 64;                                              \
        const __half* fsrc = ftp + (size_t)nc * 256;                          \
        _Pragma("unroll")                                                     \
        for (int j = 0; j < 4; j++)                                           \
            asm volatile("cp.async.cg.shared.global [%0], [%1], 16;"          \
                         :: "r"(fsAddr + so + 16 * j), "l"(fsrc + 8 * j)      \
                         : "memory");                                         \
        asm volatile("cp.async.commit_group;" ::: "memory");                  \
        uint32_t wp[16];                                                      \
        _Pragma("unroll")                                                     \
        for (int q = 0; q < 8; q++) {                                         \
            float4 ex = *(const float4*)(exrow + nc + h * 32 + 4 * q);        \
            float4 ey = *(const float4*)(eyrow + nc + h * 32 + 4 * q);        \
            float p0 = ex.x * ey.x, p1 = ex.y * ey.y;                         \
            float p2 = ex.z * ey.z, p3 = ex.w * ey.w;                         \
            psum += (p0 + p1) + (p2 + p3);                                    \
            wp[2 * q]     = f16x2(p1, p0);                                    \
            wp[2 * q + 1] = f16x2(p3, p2);                                    \
        }                                                                     \
        _Pragma("unroll")                                                     \
        for (int j = 0; j < 4; j++)                                           \
            asm volatile("st.shared.v4.b32 [%0], {%1,%2,%3,%4};"              \
                         :: "r"(wsAddr + so + 16 * j), "r"(wp[4 * j]),        \
                            "r"(wp[4 * j + 1]), "r"(wp[4 * j + 2]),           \
                            "r"(wp[4 * j + 3]) : "memory");                   \
    } while (0)

    STAGE_CHUNK(0, 0);

    for (int c = 0; c < 64; c++) {
        const int s = c & 1;
        if (c < 63) {
            STAGE_CHUNK(c + 1, s ^ 1);
            asm volatile("cp.async.wait_group 1;" ::: "memory");
        } else {
            asm volatile("cp.async.wait_group 0;" ::: "memory");
        }
        __syncthreads();

        const uint32_t so = s * STAGE;
#pragma unroll
        for (int kt = 0; kt < 4; kt++) {
            uint32_t a[2][4];
#pragma unroll
            for (int i = 0; i < 2; i++) {
                uint32_t ad = sb + so + aLane + i * 16 * APITCH + kt * 32;
                asm volatile(
                    "ldmatrix.sync.aligned.m8n8.x4.shared.b16 {%0,%1,%2,%3}, [%4];"
                    : "=r"(a[i][0]), "=r"(a[i][1]), "=r"(a[i][2]), "=r"(a[i][3])
                    : "r"(ad));
            }
#pragma unroll
            for (int pair = 0; pair < 4; pair++) {
                uint32_t bd = sb + so + BOFFR + bLane + kt * 16 * BPITCH + pair * 32;
                uint32_t b0, b1, b2, b3;
                asm volatile(
                    "ldmatrix.sync.aligned.m8n8.x4.trans.shared.b16 {%0,%1,%2,%3}, [%4];"
                    : "=r"(b0), "=r"(b1), "=r"(b2), "=r"(b3) : "r"(bd));
#pragma unroll
                for (int i = 0; i < 2; i++) {
                    float* d0 = acc[i][2 * pair];
                    float* d1 = acc[i][2 * pair + 1];
                    asm volatile(
                        "mma.sync.aligned.m16n8k16.row.col.f32.f16.f16.f32 "
                        "{%0,%1,%2,%3}, {%4,%5,%6,%7}, {%8,%9}, {%0,%1,%2,%3};"
                        : "+f"(d0[0]), "+f"(d0[1]), "+f"(d0[2]), "+f"(d0[3])
                        : "r"(a[i][0]), "r"(a[i][1]), "r"(a[i][2]), "r"(a[i][3]),
                          "r"(b0), "r"(b1));
                    asm volatile(
                        "mma.sync.aligned.m16n8k16.row.col.f32.f16.f16.f32 "
                        "{%0,%1,%2,%3}, {%4,%5,%6,%7}, {%8,%9}, {%0,%1,%2,%3};"
                        : "+f"(d1[0]), "+f"(d1[1]), "+f"(d1[2]), "+f"(d1[3])
                        : "r"(a[i][0]), "r"(a[i][1]), "r"(a[i][2]), "r"(a[i][3]),
                          "r"(b2), "r"(b3));
                }
            }
        }
        __syncthreads();
    }

    // --- exact fp32 row-sum reduction (2 partials per row) ---
    float* sm = (float*)smem;          // stage buffers are dead now
    sm[t] = psum;
    __syncthreads();
    if (t < 128) sm[256 + t] = sm[2 * t] + sm[2 * t + 1];
    __syncthreads();

    // --- epilogue: normalize, scatter to [b][e][gx][gy] ---
    const size_t obase = (size_t)b * 256 * 4096;
#pragma unroll
    for (int i = 0; i < 2; i++) {
        int lp = wm * 32 + i * 16 + g;
        int p0 = mt * 128 + lp, p1 = p0 + 8;
        float inv0 = 1.0f / (sm[256 + lp] + EPSs);
        float inv1 = 1.0f / (sm[256 + lp + 8] + EPSs);
#pragma unroll
        for (int jn = 0; jn < 8; jn++) {
            int e0 = et * 128 + wn * 64 + jn * 8 + tig * 2;
            float* o0 = out + obase + (size_t)e0 * 4096;
            float* o1 = o0 + 4096;
            o0[p0] = acc[i][jn][0] * inv0;
            o1[p0] = acc[i][jn][1] * inv0;
            o0[p1] = acc[i][jn][2] * inv1;
            o1[p1] = acc[i][jn][3] * inv1;
        }
    }
}

extern "C" void kernel_launch(void* const* d_in, const int* in_sizes, int n_in,
                              void* d_out, int out_size) {
    const float* feat = (const float*)d_in[0];  // [4,4096,256]
    const float* pos  = (const float*)d_in[1];  // [4,4096,2]
    float* out = (float*)d_out;                 // [4,256,64,64]

    cudaFuncSetAttribute(mma_kernel,
                         cudaFuncAttributeMaxDynamicSharedMemorySize, SMEMT);

    table_kernel<<<256, 256>>>(pos);
    convert_kernel<<<2048, 256>>>(feat);
    mma_kernel<<<256, 256, SMEMT>>>(out);
}

// round 10
// speedup vs baseline: 2.1707x; 2.1707x over previous
#include <cuda_runtime.h>
#include <cuda_fp16.h>
#include <cstdint>

#define SIGINV 50.0f     // 1 / (2 * 0.1^2)
#define EPSs   1e-8f

// Separable RBF tables (fp32), fp16 transposed features
__device__ float  g_ex[4][64][4096];
__device__ float  g_ey[4][64][4096];
__device__ __half g_fth[4][256][4096];   // Fth[b][e][n] = half(F[b][n][e])

// ---------------- helpers ----------------
__device__ __forceinline__ uint32_t smem_u32(const void* p) {
    uint32_t a;
    asm("{ .reg .u64 t; cvta.to.shared.u64 t, %1; cvt.u32.u64 %0, t; }"
        : "=r"(a) : "l"(p));
    return a;
}
__device__ __forceinline__ uint32_t f16x2(float hi, float lo) {
    uint32_t r;
    asm("cvt.rn.f16x2.f32 %0, %1, %2;" : "=r"(r) : "f"(hi), "f"(lo));
    return r;
}

// ---------------- pre-kernels ----------------
__global__ void __launch_bounds__(256) table_kernel(const float* __restrict__ pos) {
    int b = blockIdx.x >> 6, gi = blockIdx.x & 63;
    float gc = (float)gi * (1.0f / 63.0f);
    int t = threadIdx.x;
    const float2* p2 = (const float2*)pos + (size_t)b * 4096;
#pragma unroll
    for (int j = 0; j < 16; j++) {
        int n = t + j * 256;
        float2 p = p2[n];
        float dx = gc - p.x, dy = gc - p.y;
        g_ex[b][gi][n] = __expf(-SIGINV * dx * dx);
        g_ey[b][gi][n] = __expf(-SIGINV * dy * dy);
    }
}

__global__ void __launch_bounds__(256) transpose_kernel(const float* __restrict__ feat) {
    __shared__ float tile[32][33];
    int b = blockIdx.z, n0 = blockIdx.x * 32, e0 = blockIdx.y * 32;
    int tx = threadIdx.x & 31, ty = threadIdx.x >> 5;
    const float* src = feat + ((size_t)b * 4096 + n0) * 256 + e0;
#pragma unroll
    for (int j = 0; j < 4; j++)
        tile[ty + j * 8][tx] = src[(size_t)(ty + j * 8) * 256 + tx];
    __syncthreads();
    __half* dst = &g_fth[b][e0][n0];
#pragma unroll
    for (int j = 0; j < 4; j++)
        dst[(size_t)(ty + j * 8) * 4096 + tx] = __float2half_rn(tile[tx][ty + j * 8]);
}

// ---------------- main mma.sync fp16 kernel ----------------
// 256 blocks: blk = b*64 + mt*2 + et. Block tile: 128p x 128e.
// D = W[128 x 4096] * Fth^T, K chunks of 32 (2x m16n8k16 k-steps).
// 8 warps, warp tile 32p x 64e. Frags via ldmatrix.x4 (non-trans, pitch-80
// rows rotate 20 banks -> every 8-row phase covers all 32 banks).
#define PITCH 80
#define ASIZE (128 * PITCH)     // 10240
#define STAGE (2 * ASIZE)       // 20480
#define SMEMT (2 * STAGE)       // 40960

__global__ void __launch_bounds__(256, 2) mma_kernel(float* __restrict__ out) {
    extern __shared__ char smem[];
    uint32_t sb = smem_u32(smem);
    const int t = threadIdx.x, w = t >> 5, l = t & 31;
    const int blk = blockIdx.x, b = blk >> 6, mt = (blk >> 1) & 31, et = blk & 1;

    // --- staging maps: 2 threads per row, 16 k-values (32 B) each ---
    const int sr = t >> 1, h = t & 1;
    const float* exrow = &g_ex[b][mt * 2 + (sr >> 6)][0];
    const float* eyrow = &g_ey[b][sr & 63][0];
    const uint32_t wsAddr = sb + sr * PITCH + h * 32;
    const __half* ftrow = &g_fth[b][et * 128 + sr][0] + h * 16;
    const uint32_t fsAddr = sb + ASIZE + sr * PITCH + h * 32;

    // --- mma fragment maps: wm 0..3 (32p), wn 0..1 (64e) ---
    const int wm = w & 3, wn = w >> 2, g = l >> 2, tig = l & 3;
    // A ldmatrix lanes: p-row = l&15, k-seg = l>>4
    const uint32_t aLane = (uint32_t)((wm * 32 + (l & 15)) * PITCH + (l >> 4) * 16);
    // B ldmatrix lanes: matrix m = l>>3; e-row = (m>>1)*8 + (l&7); k-seg = m&1
    const uint32_t bLane = (uint32_t)((wn * 64 + ((l >> 4) * 8) + (l & 7)) * PITCH +
                                      ((l >> 3) & 1) * 16);

    float acc[2][8][4];
#pragma unroll
    for (int i = 0; i < 2; i++)
#pragma unroll
        for (int j = 0; j < 8; j++)
#pragma unroll
            for (int q = 0; q < 4; q++) acc[i][j][q] = 0.0f;
    float psum = 0.0f;

#define STAGE_CHUNK(c, s)                                                     \
    do {                                                                      \
        const uint32_t so = (s) * STAGE;                                      \
        const int nc = (c) * 32;                                              \
        const __half* fsrc = ftrow + nc;                                      \
        asm volatile("cp.async.cg.shared.global [%0], [%1], 16;"              \
                     :: "r"(fsAddr + so), "l"(fsrc) : "memory");              \
        asm volatile("cp.async.cg.shared.global [%0], [%1], 16;"              \
                     :: "r"(fsAddr + so + 16), "l"(fsrc + 8) : "memory");     \
        asm volatile("cp.async.commit_group;" ::: "memory");                  \
        uint32_t wp[8];                                                       \
        _Pragma("unroll")                                                     \
        for (int q = 0; q < 4; q++) {                                         \
            float4 ex = *(const float4*)(exrow + nc + h * 16 + 4 * q);        \
            float4 ey = *(const float4*)(eyrow + nc + h * 16 + 4 * q);        \
            float p0 = ex.x * ey.x, p1 = ex.y * ey.y;                         \
            float p2 = ex.z * ey.z, p3 = ex.w * ey.w;                         \
            psum += (p0 + p1) + (p2 + p3);                                    \
            wp[2 * q]     = f16x2(p1, p0);                                    \
            wp[2 * q + 1] = f16x2(p3, p2);                                    \
        }                                                                     \
        asm volatile("st.shared.v4.b32 [%0], {%1,%2,%3,%4};"                  \
                     :: "r"(wsAddr + so), "r"(wp[0]), "r"(wp[1]),             \
                        "r"(wp[2]), "r"(wp[3]) : "memory");                   \
        asm volatile("st.shared.v4.b32 [%0], {%1,%2,%3,%4};"                  \
                     :: "r"(wsAddr + so + 16), "r"(wp[4]), "r"(wp[5]),        \
                        "r"(wp[6]), "r"(wp[7]) : "memory");                   \
    } while (0)

    STAGE_CHUNK(0, 0);

    for (int c = 0; c < 128; c++) {
        const int s = c & 1;
        if (c < 127) {
            STAGE_CHUNK(c + 1, s ^ 1);
            asm volatile("cp.async.wait_group 1;" ::: "memory");
        } else {
            asm volatile("cp.async.wait_group 0;" ::: "memory");
        }
        __syncthreads();

        const uint32_t so = s * STAGE;
#pragma unroll
        for (int kt = 0; kt < 2; kt++) {
            uint32_t a[2][4];
#pragma unroll
            for (int i = 0; i < 2; i++) {
                uint32_t ad = sb + so + aLane + i * 16 * PITCH + kt * 32;
                asm volatile(
                    "ldmatrix.sync.aligned.m8n8.x4.shared.b16 {%0,%1,%2,%3}, [%4];"
                    : "=r"(a[i][0]), "=r"(a[i][1]), "=r"(a[i][2]), "=r"(a[i][3])
                    : "r"(ad));
            }
#pragma unroll
            for (int pair = 0; pair < 4; pair++) {
                uint32_t bd = sb + ASIZE + so + bLane + pair * 16 * PITCH + kt * 32;
                uint32_t b0, b1, b2, b3;
                asm volatile(
                    "ldmatrix.sync.aligned.m8n8.x4.shared.b16 {%0,%1,%2,%3}, [%4];"
                    : "=r"(b0), "=r"(b1), "=r"(b2), "=r"(b3) : "r"(bd));
#pragma unroll
                for (int i = 0; i < 2; i++) {
                    float* d0 = acc[i][2 * pair];
                    float* d1 = acc[i][2 * pair + 1];
                    asm volatile(
                        "mma.sync.aligned.m16n8k16.row.col.f32.f16.f16.f32 "
                        "{%0,%1,%2,%3}, {%4,%5,%6,%7}, {%8,%9}, {%0,%1,%2,%3};"
                        : "+f"(d0[0]), "+f"(d0[1]), "+f"(d0[2]), "+f"(d0[3])
                        : "r"(a[i][0]), "r"(a[i][1]), "r"(a[i][2]), "r"(a[i][3]),
                          "r"(b0), "r"(b1));
                    asm volatile(
                        "mma.sync.aligned.m16n8k16.row.col.f32.f16.f16.f32 "
                        "{%0,%1,%2,%3}, {%4,%5,%6,%7}, {%8,%9}, {%0,%1,%2,%3};"
                        : "+f"(d1[0]), "+f"(d1[1]), "+f"(d1[2]), "+f"(d1[3])
                        : "r"(a[i][0]), "r"(a[i][1]), "r"(a[i][2]), "r"(a[i][3]),
                          "r"(b2), "r"(b3));
                }
            }
        }
        __syncthreads();
    }

    // --- exact fp32 row-sum reduction (2 partials per row) ---
    float* sm = (float*)smem;          // stage buffers are dead now
    sm[t] = psum;
    __syncthreads();
    if (t < 128) sm[256 + t] = sm[2 * t] + sm[2 * t + 1];
    __syncthreads();

    // --- epilogue: normalize, scatter to [b][e][gx][gy] ---
    const size_t obase = (size_t)b * 256 * 4096;
#pragma unroll
    for (int i = 0; i < 2; i++) {
        int lp = wm * 32 + i * 16 + g;
        int p0 = mt * 128 + lp, p1 = p0 + 8;
        float inv0 = 1.0f / (sm[256 + lp] + EPSs);
        float inv1 = 1.0f / (sm[256 + lp + 8] + EPSs);
#pragma unroll
        for (int jn = 0; jn < 8; jn++) {
            int e0 = et * 128 + wn * 64 + jn * 8 + tig * 2;
            float* o0 = out + obase + (size_t)e0 * 4096;
            float* o1 = o0 + 4096;
            o0[p0] = acc[i][jn][0] * inv0;
            o1[p0] = acc[i][jn][1] * inv0;
            o0[p1] = acc[i][jn][2] * inv1;
            o1[p1] = acc[i][jn][3] * inv1;
        }
    }
}

extern "C" void kernel_launch(void* const* d_in, const int* in_sizes, int n_in,
                              void* d_out, int out_size) {
    const float* feat = (const float*)d_in[0];  // [4,4096,256]
    const float* pos  = (const float*)d_in[1];  // [4,4096,2]
    float* out = (float*)d_out;                 // [4,256,64,64]

    cudaFuncSetAttribute(mma_kernel,
                         cudaFuncAttributeMaxDynamicSharedMemorySize, SMEMT);

    table_kernel<<<256, 256>>>(pos);
    transpose_kernel<<<dim3(128, 8, 4), 256>>>(feat);
    mma_kernel<<<256, 256, SMEMT>>>(out);
}

// round 11
// speedup vs baseline: 2.1933x; 1.0104x over previous
#include <cuda_runtime.h>
#include <cuda_fp16.h>
#include <cstdint>

#define SIGINV 50.0f     // 1 / (2 * 0.1^2)
#define EPSs   1e-8f

// Separable RBF tables (fp32), fp16 transposed features
__device__ float  g_ex[4][64][4096];
__device__ float  g_ey[4][64][4096];
__device__ __half g_fth[4][256][4096];   // Fth[b][e][n] = half(F[b][n][e])

// ---------------- helpers ----------------
__device__ __forceinline__ uint32_t smem_u32(const void* p) {
    uint32_t a;
    asm("{ .reg .u64 t; cvta.to.shared.u64 t, %1; cvt.u32.u64 %0, t; }"
        : "=r"(a) : "l"(p));
    return a;
}
__device__ __forceinline__ uint32_t f16x2(float hi, float lo) {
    uint32_t r;
    asm("cvt.rn.f16x2.f32 %0, %1, %2;" : "=r"(r) : "f"(hi), "f"(lo));
    return r;
}

// ---------------- pre-kernels ----------------
__global__ void __launch_bounds__(256) table_kernel(const float* __restrict__ pos) {
    int b = blockIdx.x >> 6, gi = blockIdx.x & 63;
    float gc = (float)gi * (1.0f / 63.0f);
    int t = threadIdx.x;
    const float2* p2 = (const float2*)pos + (size_t)b * 4096;
#pragma unroll
    for (int j = 0; j < 16; j++) {
        int n = t + j * 256;
        float2 p = p2[n];
        float dx = gc - p.x, dy = gc - p.y;
        g_ex[b][gi][n] = __expf(-SIGINV * dx * dx);
        g_ey[b][gi][n] = __expf(-SIGINV * dy * dy);
    }
}

__global__ void __launch_bounds__(256) transpose_kernel(const float* __restrict__ feat) {
    __shared__ float tile[32][33];
    int b = blockIdx.z, n0 = blockIdx.x * 32, e0 = blockIdx.y * 32;
    int tx = threadIdx.x & 31, ty = threadIdx.x >> 5;
    const float* src = feat + ((size_t)b * 4096 + n0) * 256 + e0;
#pragma unroll
    for (int j = 0; j < 4; j++)
        tile[ty + j * 8][tx] = src[(size_t)(ty + j * 8) * 256 + tx];
    __syncthreads();
    __half* dst = &g_fth[b][e0][n0];
#pragma unroll
    for (int j = 0; j < 4; j++)
        dst[(size_t)(ty + j * 8) * 4096 + tx] = __float2half_rn(tile[tx][ty + j * 8]);
}

// ---------------- main mma.sync fp16 kernel ----------------
// 256 blocks: blk = b*64 + mt*2 + et. Block tile: 128p x 128e.
// K chunks of 32 (2x m16n8k16 k-steps). 8 warps, warp tile 32p x 64e.
// 3-stage ring buffer, ONE __syncthreads per chunk. ldmatrix.x4 frags.
#define PITCH 80
#define ASIZE (128 * PITCH)     // 10240
#define STAGE (2 * ASIZE)       // 20480
#define SMEMT (3 * STAGE)       // 61440

__global__ void __launch_bounds__(256, 2) mma_kernel(float* __restrict__ out) {
    extern __shared__ char smem[];
    uint32_t sb = smem_u32(smem);
    const int t = threadIdx.x, w = t >> 5, l = t & 31;
    const int blk = blockIdx.x, b = blk >> 6, mt = (blk >> 1) & 31, et = blk & 1;

    // --- staging maps: 2 threads per row, 16 k-values (32 B) each ---
    const int sr = t >> 1, h = t & 1;
    const float* exrow = &g_ex[b][mt * 2 + (sr >> 6)][0];
    const float* eyrow = &g_ey[b][sr & 63][0];
    const uint32_t wsAddr = sb + sr * PITCH + h * 32;
    const __half* ftrow = &g_fth[b][et * 128 + sr][0] + h * 16;
    const uint32_t fsAddr = sb + ASIZE + sr * PITCH + h * 32;

    // --- mma fragment maps: wm 0..3 (32p), wn 0..1 (64e) ---
    const int wm = w & 3, wn = w >> 2, g = l >> 2, tig = l & 3;
    const uint32_t aLane = (uint32_t)((wm * 32 + (l & 15)) * PITCH + (l >> 4) * 16);
    const uint32_t bLane = (uint32_t)((wn * 64 + ((l >> 4) * 8) + (l & 7)) * PITCH +
                                      ((l >> 3) & 1) * 16);

    float acc[2][8][4];
#pragma unroll
    for (int i = 0; i < 2; i++)
#pragma unroll
        for (int j = 0; j < 8; j++)
#pragma unroll
            for (int q = 0; q < 4; q++) acc[i][j][q] = 0.0f;
    float psum = 0.0f;

#define STAGE_CHUNK(c, so)                                                    \
    do {                                                                      \
        const int nc = (c) * 32;                                              \
        const __half* fsrc = ftrow + nc;                                      \
        asm volatile("cp.async.cg.shared.global [%0], [%1], 16;"              \
                     :: "r"(fsAddr + (so)), "l"(fsrc) : "memory");            \
        asm volatile("cp.async.cg.shared.global [%0], [%1], 16;"              \
                     :: "r"(fsAddr + (so) + 16), "l"(fsrc + 8) : "memory");   \
        asm volatile("cp.async.commit_group;" ::: "memory");                  \
        uint32_t wp[8];                                                       \
        _Pragma("unroll")                                                     \
        for (int q = 0; q < 4; q++) {                                         \
            float4 ex = *(const float4*)(exrow + nc + h * 16 + 4 * q);        \
            float4 ey = *(const float4*)(eyrow + nc + h * 16 + 4 * q);        \
            float p0 = ex.x * ey.x, p1 = ex.y * ey.y;                         \
            float p2 = ex.z * ey.z, p3 = ex.w * ey.w;                         \
            psum += (p0 + p1) + (p2 + p3);                                    \
            wp[2 * q]     = f16x2(p1, p0);                                    \
            wp[2 * q + 1] = f16x2(p3, p2);                                    \
        }                                                                     \
        asm volatile("st.shared.v4.b32 [%0], {%1,%2,%3,%4};"                  \
                     :: "r"(wsAddr + (so)), "r"(wp[0]), "r"(wp[1]),           \
                        "r"(wp[2]), "r"(wp[3]) : "memory");                   \
        asm volatile("st.shared.v4.b32 [%0], {%1,%2,%3,%4};"                  \
                     :: "r"(wsAddr + (so) + 16), "r"(wp[4]), "r"(wp[5]),      \
                        "r"(wp[6]), "r"(wp[7]) : "memory");                   \
    } while (0)

    STAGE_CHUNK(0, 0);
    STAGE_CHUNK(1, STAGE);

    uint32_t soc = 0, son = 2 * STAGE;
    for (int c = 0; c < 128; c++) {
        if (c < 127)
            asm volatile("cp.async.wait_group 1;" ::: "memory");
        else
            asm volatile("cp.async.wait_group 0;" ::: "memory");
        __syncthreads();
        if (c < 126) {
            STAGE_CHUNK(c + 2, son);
            son = (son == 2 * STAGE) ? 0 : son + STAGE;
        }

        const uint32_t so = soc;
        soc = (soc == 2 * STAGE) ? 0 : soc + STAGE;
#pragma unroll
        for (int kt = 0; kt < 2; kt++) {
            uint32_t a[2][4];
#pragma unroll
            for (int i = 0; i < 2; i++) {
                uint32_t ad = sb + so + aLane + i * 16 * PITCH + kt * 32;
                asm volatile(
                    "ldmatrix.sync.aligned.m8n8.x4.shared.b16 {%0,%1,%2,%3}, [%4];"
                    : "=r"(a[i][0]), "=r"(a[i][1]), "=r"(a[i][2]), "=r"(a[i][3])
                    : "r"(ad));
            }
#pragma unroll
            for (int pair = 0; pair < 4; pair++) {
                uint32_t bd = sb + ASIZE + so + bLane + pair * 16 * PITCH + kt * 32;
                uint32_t b0, b1, b2, b3;
                asm volatile(
                    "ldmatrix.sync.aligned.m8n8.x4.shared.b16 {%0,%1,%2,%3}, [%4];"
                    : "=r"(b0), "=r"(b1), "=r"(b2), "=r"(b3) : "r"(bd));
#pragma unroll
                for (int i = 0; i < 2; i++) {
                    float* d0 = acc[i][2 * pair];
                    float* d1 = acc[i][2 * pair + 1];
                    asm volatile(
                        "mma.sync.aligned.m16n8k16.row.col.f32.f16.f16.f32 "
                        "{%0,%1,%2,%3}, {%4,%5,%6,%7}, {%8,%9}, {%0,%1,%2,%3};"
                        : "+f"(d0[0]), "+f"(d0[1]), "+f"(d0[2]), "+f"(d0[3])
                        : "r"(a[i][0]), "r"(a[i][1]), "r"(a[i][2]), "r"(a[i][3]),
                          "r"(b0), "r"(b1));
                    asm volatile(
                        "mma.sync.aligned.m16n8k16.row.col.f32.f16.f16.f32 "
                        "{%0,%1,%2,%3}, {%4,%5,%6,%7}, {%8,%9}, {%0,%1,%2,%3};"
                        : "+f"(d1[0]), "+f"(d1[1]), "+f"(d1[2]), "+f"(d1[3])
                        : "r"(a[i][0]), "r"(a[i][1]), "r"(a[i][2]), "r"(a[i][3]),
                          "r"(b2), "r"(b3));
                }
            }
        }
    }

    // --- exact fp32 row-sum reduction (2 partials per row) ---
    // (buffer 0 region is safe: last reads of it were chunk 126, barriered at 127)
    float* sm = (float*)smem;
    sm[t] = psum;
    __syncthreads();
    if (t < 128) sm[256 + t] = sm[2 * t] + sm[2 * t + 1];
    __syncthreads();

    float inv[2][2];
#pragma unroll
    for (int i = 0; i < 2; i++) {
        int lp = wm * 32 + i * 16 + g;
        inv[i][0] = 1.0f / (sm[256 + lp] + EPSs);
        inv[i][1] = 1.0f / (sm[256 + lp + 8] + EPSs);
    }

    // --- epilogue: 4 x 32e slabs through smem -> coalesced float4 stores ---
    float* sbuf = sm + 512;                   // 32 x 132 floats = 16896 B
    const size_t obase = (size_t)b * 256 * 4096;
    const int er = t >> 3, seg = t & 7;
#pragma unroll
    for (int es = 0; es < 4; es++) {
        if ((es >> 1) == wn) {
            const int jbase = (es & 1) * 4;
#pragma unroll
            for (int jj = 0; jj < 4; jj++) {
                int jn = jbase + jj;
                int erow = jj * 8 + tig * 2;
#pragma unroll
                for (int i = 0; i < 2; i++) {
                    int pl = wm * 32 + i * 16 + g;
                    sbuf[erow * 132 + pl]           = acc[i][jn][0] * inv[i][0];
                    sbuf[(erow + 1) * 132 + pl]     = acc[i][jn][1] * inv[i][0];
                    sbuf[erow * 132 + pl + 8]       = acc[i][jn][2] * inv[i][1];
                    sbuf[(erow + 1) * 132 + pl + 8] = acc[i][jn][3] * inv[i][1];
                }
            }
        }
        __syncthreads();
        int e_glob = et * 128 + es * 32 + er;
        const float4* src = (const float4*)&sbuf[er * 132 + seg * 16];
        float* o = out + obase + (size_t)e_glob * 4096 + mt * 128 + seg * 16;
        float4 v0 = src[0], v1 = src[1], v2 = src[2], v3 = src[3];
        ((float4*)o)[0] = v0;
        ((float4*)o)[1] = v1;
        ((float4*)o)[2] = v2;
        ((float4*)o)[3] = v3;
        __syncthreads();
    }
}

extern "C" void kernel_launch(void* const* d_in, const int* in_sizes, int n_in,
                              void* d_out, int out_size) {
    const float* feat = (const float*)d_in[0];  // [4,4096,256]
    const float* pos  = (const float*)d_in[1];  // [4,4096,2]
    float* out = (float*)d_out;                 // [4,256,64,64]

    cudaFuncSetAttribute(mma_kernel,
                         cudaFuncAttributeMaxDynamicSharedMemorySize, SMEMT);

    table_kernel<<<256, 256>>>(pos);
    transpose_kernel<<<dim3(128, 8, 4), 256>>>(feat);
    mma_kernel<<<256, 256, SMEMT>>>(out);
}